// round 13
// baseline (speedup 1.0000x reference)
#include <cuda_runtime.h>
#include <cstddef>
#include <cstdint>
#include <math.h>

// CTC batch cost (Keras semantics): B=256, T=512, V=256, L=64, blank=V-1
// loss[b] = -log P(y_true[b] | y_pred[b]), logp = log(y_pred + 1e-7)
//
// R13: bidirectional meet-in-the-middle DP + COMPACT chunk-gather cp.async.
//   R8/R11/R12 (three independent memory structures) all pinned at
//   5.0-5.1TB/s -> treat that as the empirical BW ceiling; cut traffic.
//   Each warp precomputes the 64-bit mask of needed 16B chunks per row
//   (la>>2, lb>>2 over all lanes, + chunk 63 for blank): ~42 of 64 chunks.
//   Per row, lane issues predicated cp.async-16B for chunk ranks lane and
//   lane+32 into COMPACTED smem rows (stride nch*16 ~ 672B vs 1024B).
//   Gather offsets into the compact row are precomputed per lane.
//   5-slot ring keeps ~21KB outstanding per warp (R12 level).
//
// Block = 64 threads, one element: warp0 fwd t=0..255, warp1 bwd t=511..256.
// DP math identical to R8/R12 (lane j owns Ba=s4j, La=s4j+1, Bb=s4j+2,
// Lb=s4j+3; lane31 B64=s128; per-lane pow2 scaling, renorm every 8 steps;
// combine P = sum_s alpha_255(s)*B_256(s) in log2 domain).

#define B_   256
#define T_   512
#define V_   256
#define L_   64
#define CH   8
#define HT   (T_ / 2)
#define NCH  (HT / CH)        // 32 chunks per direction
#define NSL  5                // ring slots per warp
#define WRINGB (NSL * CH * 1024)        // worst-case ring bytes per warp
#define SMEM_DYN (2 * WRINGB)           // 81920 B per block
#define EPS  1e-7f
#define FULL 0xFFFFFFFFu
#define MAXGAP 64
#define LN2F 0.6931471805599453f

__device__ __forceinline__ float exp2i(int e)
{
    if (e <= -127) return 0.0f;
    if (e > 127)   e = 127;
    return __int_as_float((e + 127) << 23);
}

__device__ __forceinline__ void cp_async16(uint32_t saddr, const void* gaddr)
{
    asm volatile("cp.async.cg.shared.global [%0], [%1], 16;\n"
                 :: "r"(saddr), "l"(gaddr) : "memory");
}

extern __shared__ char dynsmem[];

__global__ void __launch_bounds__(64)
ctc_forward_kernel(const int* __restrict__ y_true,
                   const float* __restrict__ y_pred,
                   float* __restrict__ out)
{
    __shared__ float sBv[32][5];       // backward B-values per lane
    __shared__ int   sBo[32];          // backward off per lane

    const int b    = blockIdx.x;
    const int wid  = threadIdx.x >> 5;   // 0 = forward, 1 = backward
    const int lane = threadIdx.x & 31;
    const int dir  = wid;

    const float* base = y_pred + (size_t)b * (size_t)(T_ * V_);
    const int* lrow = y_true + b * L_;
    const int la = lrow[2 * lane];
    const int lb = lrow[2 * lane + 1];
    const int lprev = __shfl_up_sync(FULL, lb, 1);    // label[2j-1]
    const int lnext = __shfl_down_sync(FULL, la, 1);  // label[2j+2]
    const float sa  = (la != lprev) ? 1.0f : 0.0f;    // lane0 irrelevant
    const float saN = (lnext != lb) ? 1.0f : 0.0f;    // lane31 irrelevant
    const float sb  = (lb != la) ? 1.0f : 0.0f;

    // ---- needed-chunk mask (16B chunks of the 1KB row) ----
    unsigned mlo = 0, mhi = 0;
    {
        int ca = la >> 2, cb = lb >> 2;
        if (ca < 32) mlo |= 1u << ca; else mhi |= 1u << (ca - 32);
        if (cb < 32) mlo |= 1u << cb; else mhi |= 1u << (cb - 32);
    }
    mhi |= 0x80000000u;     // blank (col 255) lives in chunk 63
#pragma unroll
    for (int o = 16; o > 0; o >>= 1) {
        mlo |= __shfl_xor_sync(FULL, mlo, o);
        mhi |= __shfl_xor_sync(FULL, mhi, o);
    }
    const int nlo = __popc(mlo);
    const int nch = nlo + __popc(mhi);           // ~42 typically, <=64
    const int RS    = nch * 16;                  // compact row stride
    const int slotB = CH * RS;                   // compact slot bytes

    // rank of a chunk = #set bits below it
#define CRANK(c) ((c) < 32 ? __popc(mlo & ((1u << ((c) & 31)) - 1u))          \
                           : nlo + __popc(mhi & ((1u << ((c) & 31)) - 1u)))
    const int offa = CRANK(la >> 2) * 16 + (la & 3) * 4;
    const int offb = CRANK(lb >> 2) * 16 + (lb & 3) * 4;
    const int offq = (nch - 1) * 16 + 12;        // chunk 63 is last; col&3=3

    // source chunk index for ranks lane and lane+32
    int chk0 = -1, chk1 = -1;
    {
        int cnt = 0;
#pragma unroll
        for (int c = 0; c < 64; ++c) {
            bool set = (c < 32) ? ((mlo >> c) & 1u) : ((mhi >> (c - 32)) & 1u);
            if (set) {
                if (cnt == lane)      chk0 = c;
                if (cnt == lane + 32) chk1 = c;
                ++cnt;
            }
        }
    }
    const bool h0 = (chk0 >= 0);
    const bool h1 = (chk1 >= 0);
    const long long so0 = (long long)chk0 * 16;
    const long long so1 = (long long)chk1 * 16;

    // Per-warp ring (worst-case region; actual stride slotB)
    char* ring = dynsmem + wid * WRINGB;
    const uint32_t rbase = (uint32_t)__cvta_generic_to_shared(ring);
    const char* sbase = (const char*)base
                      + (dir ? (size_t)(T_ - 1) * (V_ * 4) : 0);
    const long long srow = dir ? -(long long)(V_ * 4) : (V_ * 4);

    float Ba, La_v, Bb, Lb_v, B64;
    int   off = 0;
    float corr;
    float va[CH], vb[CH], vq[CH];

    // ---- compact gather of one chunk (8 rows) into a ring slot ----
#define ISSUE_SLOT(c)                                                       \
    do {                                                                    \
        uint32_t _sp = rbase + (uint32_t)(((c) % NSL) * slotB);             \
        const char* _g0 = sbase + (long long)(c) * CH * srow;               \
        _Pragma("unroll")                                                   \
        for (int _i = 0; _i < CH; ++_i) {                                   \
            const char* _r = _g0 + (long long)_i * srow;                    \
            uint32_t _d = _sp + _i * RS;                                    \
            if (h0) cp_async16(_d + lane * 16,        _r + so0);            \
            if (h1) cp_async16(_d + (lane + 32) * 16, _r + so1);            \
        }                                                                   \
        asm volatile("cp.async.commit_group;\n" ::: "memory");              \
    } while (0)

    // ---- gather chunk values from the compact slot into registers ----
#define READ_SLOT(c)                                                        \
    do {                                                                    \
        const char* _rp = ring + ((c) % NSL) * slotB;                       \
        _Pragma("unroll")                                                   \
        for (int _i = 0; _i < CH; ++_i) {                                   \
            const char* _row = _rp + _i * RS;                               \
            va[_i] = *(const float*)(_row + offa);                          \
            vb[_i] = *(const float*)(_row + offb);                          \
            vq[_i] = *(const float*)(_row + offq);                          \
        }                                                                   \
    } while (0)

#define WAITG(n)                                                            \
    do {                                                                    \
        asm volatile("cp.async.wait_group " #n ";\n" ::: "memory");         \
        __syncwarp();                                                       \
    } while (0)

    // ---- DP steps (identical math to R8/R12) ----
#define STEP_F(pa_, pb_, pq_)                                       \
    do {                                                            \
        float _pa = (pa_) + EPS;                                    \
        float _pb = (pb_) + EPS;                                    \
        float _pq = (pq_) + EPS;                                    \
        float _tp = __shfl_up_sync(FULL, Lb_v, 1) * corr;           \
        float _nLa = (La_v + Ba + sa * _tp) * _pa;                  \
        float _nLb = (Lb_v + Bb + sb * La_v) * _pb;                 \
        float _nBa = (Ba + _tp) * _pq;                              \
        float _nBb = (Bb + La_v) * _pq;                             \
        float _nB6 = (B64 + Lb_v) * _pq;                            \
        La_v = _nLa; Lb_v = _nLb; Ba = _nBa; Bb = _nBb; B64 = _nB6; \
    } while (0)

#define STEP_B(pa_, pb_, pq_)                                       \
    do {                                                            \
        float _pa = (pa_) + EPS;                                    \
        float _pb = (pb_) + EPS;                                    \
        float _pq = (pq_) + EPS;                                    \
        float _nb = __shfl_down_sync(FULL, Ba, 1);                  \
        float _nl = __shfl_down_sync(FULL, La_v, 1);                \
        _nb = (lane == 31) ? B64 : _nb * corr;                      \
        _nl = (lane == 31) ? 0.0f : _nl * corr;                     \
        float _nBa = (Ba + La_v) * _pq;                             \
        float _nLa = (La_v + Bb + sb * Lb_v) * _pa;                 \
        float _nBb = (Bb + Lb_v) * _pq;                             \
        float _nLb = (Lb_v + _nb + saN * _nl) * _pb;                \
        float _nB6 = B64 * _pq;                                     \
        La_v = _nLa; Lb_v = _nLb; Ba = _nBa; Bb = _nBb; B64 = _nB6; \
    } while (0)

#define RENORM_F()                                                          \
    do {                                                                    \
        float _m = fmaxf(fmaxf(fmaxf(La_v, Lb_v), fmaxf(Ba, Bb)), B64);     \
        bool _dead = (_m <= 0.0f);                                          \
        int _iexp = _dead ? 0 : (((__float_as_int(_m) >> 23) & 255) - 127); \
        if (_iexp < -120) _iexp = -120;                                     \
        int _offnew = off + _iexp;                                          \
        int _up = __shfl_up_sync(FULL, _offnew, 1);                         \
        int _offfin;                                                        \
        if (lane == 0)      _offfin = _offnew;                              \
        else if (_dead)     _offfin = _up;                                  \
        else                _offfin = (_up - MAXGAP > _offnew)              \
                                        ? (_up - MAXGAP) : _offnew;         \
        if (!_dead) {                                                       \
            float _f = exp2i(off - _offfin);                                \
            La_v *= _f; Lb_v *= _f; Ba *= _f; Bb *= _f; B64 *= _f;          \
        }                                                                   \
        off = _offfin;                                                      \
        int _upf = __shfl_up_sync(FULL, _offfin, 1);                        \
        int _dd = _upf - _offfin;                                           \
        if (_dd > 100) _dd = 100;                                           \
        corr = (lane == 0) ? 0.0f : exp2i(_dd);                             \
    } while (0)

#define RENORM_B()                                                          \
    do {                                                                    \
        float _m = fmaxf(fmaxf(fmaxf(La_v, Lb_v), fmaxf(Ba, Bb)), B64);     \
        bool _dead = (_m <= 0.0f);                                          \
        int _iexp = _dead ? 0 : (((__float_as_int(_m) >> 23) & 255) - 127); \
        if (_iexp < -120) _iexp = -120;                                     \
        int _offnew = off + _iexp;                                          \
        int _dn = __shfl_down_sync(FULL, _offnew, 1);                       \
        int _offfin;                                                        \
        if (lane == 31)     _offfin = _offnew;                              \
        else if (_dead)     _offfin = _dn;                                  \
        else                _offfin = (_dn - MAXGAP > _offnew)              \
                                        ? (_dn - MAXGAP) : _offnew;         \
        if (!_dead) {                                                       \
            float _f = exp2i(off - _offfin);                                \
            La_v *= _f; Lb_v *= _f; Ba *= _f; Bb *= _f; B64 *= _f;          \
        }                                                                   \
        off = _offfin;                                                      \
        int _dnf = __shfl_down_sync(FULL, _offfin, 1);                      \
        int _dd = _dnf - _offfin;                                           \
        if (_dd > 100) _dd = 100;                                           \
        corr = (lane == 31) ? 0.0f : exp2i(_dd);                            \
    } while (0)

#define DO_STEPS(STEPM)                                                 \
    do {                                                                \
        _Pragma("unroll")                                               \
        for (int _s = 0; _s < CH; ++_s) STEPM(va[_s], vb[_s], vq[_s]);  \
    } while (0)

    // Pipeline: prime 5 slots; steady state waits for slot c (4 younger
    // groups in flight), gathers it, refills with c+5, runs the DP chunk.
#define RUN_DIR(STEPM, RENM)                                            \
    do {                                                                \
        ISSUE_SLOT(0); ISSUE_SLOT(1); ISSUE_SLOT(2); ISSUE_SLOT(3);     \
        ISSUE_SLOT(4);                                                  \
        for (int c = 0; c <= NCH - 5; ++c) {                            \
            WAITG(4);                                                   \
            READ_SLOT(c);                                               \
            if (c + 5 < NCH) ISSUE_SLOT(c + 5);                         \
            DO_STEPS(STEPM); RENM();                                    \
        }                                                               \
        WAITG(3); READ_SLOT(NCH - 4); DO_STEPS(STEPM); RENM();          \
        WAITG(2); READ_SLOT(NCH - 3); DO_STEPS(STEPM); RENM();          \
        WAITG(1); READ_SLOT(NCH - 2); DO_STEPS(STEPM); RENM();          \
        WAITG(0); READ_SLOT(NCH - 1); DO_STEPS(STEPM); RENM();          \
    } while (0)

    if (dir == 0) {
        // -------- forward: t = 0..255 --------
        Ba = (lane == 0) ? 1.0f : 0.0f;
        La_v = Lb_v = Bb = B64 = 0.0f;
        corr = (lane == 0) ? 0.0f : 1.0f;
        RUN_DIR(STEP_F, RENORM_F);
    } else {
        // -------- backward: t = 511..256 --------
        Ba = La_v = Bb = Lb_v = 0.0f;
        B64 = (lane == 31) ? 1.0f : 0.0f;
        corr = (lane == 31) ? 0.0f : 1.0f;
        RUN_DIR(STEP_B, RENORM_B);

        // Publish B_{256}(s) = beta(s) + beta(s+1) + skip(s+2)*beta(s+2)
        {
            float _nb = __shfl_down_sync(FULL, Ba, 1);
            float _nl = __shfl_down_sync(FULL, La_v, 1);
            _nb = (lane == 31) ? B64 : _nb * corr;
            _nl = (lane == 31) ? 0.0f : _nl * corr;
            sBv[lane][0] = Ba + La_v;                  // B at s=4j
            sBv[lane][1] = La_v + Bb + sb * Lb_v;      // B at s=4j+1
            sBv[lane][2] = Bb + Lb_v;                  // B at s=4j+2
            sBv[lane][3] = Lb_v + _nb + saN * _nl;     // B at s=4j+3
            sBv[lane][4] = B64;                        // B at s=128
            sBo[lane] = off;
        }
    }

    __syncthreads();

    if (dir == 0) {
        // dot over this lane's states; true value = dot * 2^(offA+offB)
        float dot = Ba * sBv[lane][0] + La_v * sBv[lane][1]
                  + Bb * sBv[lane][2] + Lb_v * sBv[lane][3];
        if (lane == 31) dot += B64 * sBv[lane][4];
        int e = off + sBo[lane];

        int   ep;    // normalized exponent of lane contribution
        float m;     // mantissa in [1,2)
        if (dot > 0.0f) {
            int ie = ((__float_as_int(dot) >> 23) & 255) - 127;
            m  = dot * exp2i(-ie);
            ep = e + ie;
        } else {
            m  = 0.0f;
            ep = -0x40000000;
        }
        int emax = ep;
#pragma unroll
        for (int o = 16; o > 0; o >>= 1)
            emax = max(emax, __shfl_xor_sync(FULL, emax, o));
        float part = m * exp2i(ep - emax);
#pragma unroll
        for (int o = 16; o > 0; o >>= 1)
            part += __shfl_xor_sync(FULL, part, o);
        if (lane == 0)
            out[b] = -((__log2f(part) + (float)emax) * LN2F);
    }
}

extern "C" void kernel_launch(void* const* d_in, const int* in_sizes, int n_in,
                              void* d_out, int out_size)
{
    // Identify inputs by element count: y_true is B*L int32, y_pred is B*T*V f32
    const int* y_true = nullptr;
    const float* y_pred = nullptr;
    if (in_sizes[0] == B_ * L_) {
        y_true = (const int*)d_in[0];
        y_pred = (const float*)d_in[1];
    } else {
        y_true = (const int*)d_in[1];
        y_pred = (const float*)d_in[0];
    }
    float* out = (float*)d_out;

    // 80KB dynamic smem ring per block (worst case; idempotent attribute set)
    cudaFuncSetAttribute(ctc_forward_kernel,
                         cudaFuncAttributeMaxDynamicSharedMemorySize,
                         SMEM_DYN);

    // One 64-thread block per batch element: warp0 fwd DP, warp1 bwd DP
    ctc_forward_kernel<<<B_, 64, SMEM_DYN>>>(y_true, y_pred, out);
}

// round 14
// speedup vs baseline: 1.0702x; 1.0702x over previous
#include <cuda_runtime.h>
#include <cstddef>
#include <cstdint>
#include <math.h>

// CTC batch cost (Keras semantics): B=256, T=512, V=256, L=64, blank=V-1
// loss[b] = -log P(y_true[b] | y_pred[b]), logp = log(y_pred + 1e-7)
//
// R14 = R12 (coalesced full-row cp.async ring, best structure: 28.7us)
//     + PREDICATED SECTOR SKIP with STATIC layout.
//   R13 taught: (a) DRAM traffic is 32B-sector-quantized -> 16B compaction
//   saved nothing at DRAM; (b) dynamic compact strides bloat addressing ALU
//   and registers, slowing the warp's own issue rate. Fix: keep R12's
//   full-row smem layout and static strides EXACTLY, but skip the cp.async
//   for 16B chunks that contain no needed column. Lane owns chunks lane and
//   lane+32; two precomputed predicates from the warp-wide needed-chunk
//   mask (la>>2, lb>>2 across lanes, + chunk 63 for blank). ~42/64 chunks
//   issued -> ~28.6/32 DRAM sectors -> traffic 134MB -> ~118MB.
//
// Block = 64 threads, one element: warp0 fwd t=0..255, warp1 bwd t=511..256.
// DP math identical to R8/R12 (lane j owns Ba=s4j, La=s4j+1, Bb=s4j+2,
// Lb=s4j+3; lane31 B64=s128; per-lane pow2 scaling, renorm every 8 steps;
// combine P = sum_s alpha_255(s)*B_256(s) in log2 domain).

#define B_   256
#define T_   512
#define V_   256
#define L_   64
#define CH   8
#define HT   (T_ / 2)
#define NCH  (HT / CH)        // 32 chunks per direction
#define NSL  4                // ring slots per warp
#define ROWB 1040             // row stride in ring: 1024B data + 16B pad
#define SLOTB (CH * ROWB)     // 8320 B
#define RINGB (NSL * SLOTB)   // 33280 B per warp
#define SMEM_DYN (2 * RINGB)  // 66560 B per block
#define EPS  1e-7f
#define FULL 0xFFFFFFFFu
#define MAXGAP 64
#define LN2F 0.6931471805599453f

__device__ __forceinline__ float exp2i(int e)
{
    if (e <= -127) return 0.0f;
    if (e > 127)   e = 127;
    return __int_as_float((e + 127) << 23);
}

__device__ __forceinline__ void cp_async16(uint32_t saddr, const void* gaddr)
{
    asm volatile("cp.async.cg.shared.global [%0], [%1], 16;\n"
                 :: "r"(saddr), "l"(gaddr) : "memory");
}

extern __shared__ char dynsmem[];

__global__ void __launch_bounds__(64)
ctc_forward_kernel(const int* __restrict__ y_true,
                   const float* __restrict__ y_pred,
                   float* __restrict__ out)
{
    __shared__ float sBv[32][5];       // backward B-values per lane
    __shared__ int   sBo[32];          // backward off per lane

    const int b    = blockIdx.x;
    const int wid  = threadIdx.x >> 5;   // 0 = forward, 1 = backward
    const int lane = threadIdx.x & 31;
    const int dir  = wid;

    const float* base = y_pred + (size_t)b * (size_t)(T_ * V_);
    const int* lrow = y_true + b * L_;
    const int la = lrow[2 * lane];
    const int lb = lrow[2 * lane + 1];
    const int lprev = __shfl_up_sync(FULL, lb, 1);    // label[2j-1]
    const int lnext = __shfl_down_sync(FULL, la, 1);  // label[2j+2]
    const float sa  = (la != lprev) ? 1.0f : 0.0f;    // lane0 irrelevant
    const float saN = (lnext != lb) ? 1.0f : 0.0f;    // lane31 irrelevant
    const float sb  = (lb != la) ? 1.0f : 0.0f;

    // ---- needed-chunk mask (16B chunks of the 1KB row) ----
    // chunk c covers columns [4c, 4c+4); lane issues chunks lane, lane+32.
    unsigned mlo = 0, mhi = 0;
    {
        int ca = la >> 2, cb = lb >> 2;
        if (ca < 32) mlo |= 1u << ca; else mhi |= 1u << (ca - 32);
        if (cb < 32) mlo |= 1u << cb; else mhi |= 1u << (cb - 32);
    }
    mhi |= 0x80000000u;     // blank (col 255) lives in chunk 63
#pragma unroll
    for (int o = 16; o > 0; o >>= 1) {
        mlo |= __shfl_xor_sync(FULL, mlo, o);
        mhi |= __shfl_xor_sync(FULL, mhi, o);
    }
    const bool need0 = (mlo >> lane) & 1u;   // chunk lane      (bytes lane*16)
    const bool need1 = (mhi >> lane) & 1u;   // chunk lane+32   (bytes lane*16+512)

    // Per-warp ring (static layout identical to R12)
    char* ring = dynsmem + wid * RINGB;
    const uint32_t rbase = (uint32_t)__cvta_generic_to_shared(ring);
    const char* sbase = (const char*)base
                      + (dir ? (size_t)(T_ - 1) * (V_ * 4) : 0);
    const long long srow = dir ? -(long long)(V_ * 4) : (V_ * 4);

    float Ba, La_v, Bb, Lb_v, B64;
    int   off = 0;
    float corr;
    float va[CH], vb[CH], vq[CH];

    // ---- predicated stream of one chunk (8 rows) into a ring slot ----
#define ISSUE_SLOT(c)                                                       \
    do {                                                                    \
        uint32_t _sp = rbase + (uint32_t)(((c) & (NSL - 1)) * SLOTB)        \
                     + (uint32_t)(lane * 16);                               \
        const char* _g = sbase + (long long)(c) * CH * srow + lane * 16;    \
        _Pragma("unroll")                                                   \
        for (int _i = 0; _i < CH; ++_i) {                                   \
            if (need0) cp_async16(_sp,       _g);                           \
            if (need1) cp_async16(_sp + 512, _g + 512);                     \
            _sp += ROWB; _g += srow;                                        \
        }                                                                   \
        asm volatile("cp.async.commit_group;\n" ::: "memory");              \
    } while (0)

    // ---- gather chunk values from the ring slot into registers ----
#define READ_SLOT(c)                                                        \
    do {                                                                    \
        const char* _rp = ring + ((c) & (NSL - 1)) * SLOTB;                 \
        _Pragma("unroll")                                                   \
        for (int _i = 0; _i < CH; ++_i) {                                   \
            const float* _row = (const float*)(_rp + _i * ROWB);            \
            va[_i] = _row[la];                                              \
            vb[_i] = _row[lb];                                              \
            vq[_i] = _row[V_ - 1];                                          \
        }                                                                   \
    } while (0)

#define WAITG(n)                                                            \
    do {                                                                    \
        asm volatile("cp.async.wait_group " #n ";\n" ::: "memory");         \
        __syncwarp();                                                       \
    } while (0)

    // ---- DP steps (identical math to R8/R12) ----
#define STEP_F(pa_, pb_, pq_)                                       \
    do {                                                            \
        float _pa = (pa_) + EPS;                                    \
        float _pb = (pb_) + EPS;                                    \
        float _pq = (pq_) + EPS;                                    \
        float _tp = __shfl_up_sync(FULL, Lb_v, 1) * corr;           \
        float _nLa = (La_v + Ba + sa * _tp) * _pa;                  \
        float _nLb = (Lb_v + Bb + sb * La_v) * _pb;                 \
        float _nBa = (Ba + _tp) * _pq;                              \
        float _nBb = (Bb + La_v) * _pq;                             \
        float _nB6 = (B64 + Lb_v) * _pq;                            \
        La_v = _nLa; Lb_v = _nLb; Ba = _nBa; Bb = _nBb; B64 = _nB6; \
    } while (0)

#define STEP_B(pa_, pb_, pq_)                                       \
    do {                                                            \
        float _pa = (pa_) + EPS;                                    \
        float _pb = (pb_) + EPS;                                    \
        float _pq = (pq_) + EPS;                                    \
        float _nb = __shfl_down_sync(FULL, Ba, 1);                  \
        float _nl = __shfl_down_sync(FULL, La_v, 1);                \
        _nb = (lane == 31) ? B64 : _nb * corr;                      \
        _nl = (lane == 31) ? 0.0f : _nl * corr;                     \
        float _nBa = (Ba + La_v) * _pq;                             \
        float _nLa = (La_v + Bb + sb * Lb_v) * _pa;                 \
        float _nBb = (Bb + Lb_v) * _pq;                             \
        float _nLb = (Lb_v + _nb + saN * _nl) * _pb;                \
        float _nB6 = B64 * _pq;                                     \
        La_v = _nLa; Lb_v = _nLb; Ba = _nBa; Bb = _nBb; B64 = _nB6; \
    } while (0)

#define RENORM_F()                                                          \
    do {                                                                    \
        float _m = fmaxf(fmaxf(fmaxf(La_v, Lb_v), fmaxf(Ba, Bb)), B64);     \
        bool _dead = (_m <= 0.0f);                                          \
        int _iexp = _dead ? 0 : (((__float_as_int(_m) >> 23) & 255) - 127); \
        if (_iexp < -120) _iexp = -120;                                     \
        int _offnew = off + _iexp;                                          \
        int _up = __shfl_up_sync(FULL, _offnew, 1);                         \
        int _offfin;                                                        \
        if (lane == 0)      _offfin = _offnew;                              \
        else if (_dead)     _offfin = _up;                                  \
        else                _offfin = (_up - MAXGAP > _offnew)              \
                                        ? (_up - MAXGAP) : _offnew;         \
        if (!_dead) {                                                       \
            float _f = exp2i(off - _offfin);                                \
            La_v *= _f; Lb_v *= _f; Ba *= _f; Bb *= _f; B64 *= _f;          \
        }                                                                   \
        off = _offfin;                                                      \
        int _upf = __shfl_up_sync(FULL, _offfin, 1);                        \
        int _dd = _upf - _offfin;                                           \
        if (_dd > 100) _dd = 100;                                           \
        corr = (lane == 0) ? 0.0f : exp2i(_dd);                             \
    } while (0)

#define RENORM_B()                                                          \
    do {                                                                    \
        float _m = fmaxf(fmaxf(fmaxf(La_v, Lb_v), fmaxf(Ba, Bb)), B64);     \
        bool _dead = (_m <= 0.0f);                                          \
        int _iexp = _dead ? 0 : (((__float_as_int(_m) >> 23) & 255) - 127); \
        if (_iexp < -120) _iexp = -120;                                     \
        int _offnew = off + _iexp;                                          \
        int _dn = __shfl_down_sync(FULL, _offnew, 1);                       \
        int _offfin;                                                        \
        if (lane == 31)     _offfin = _offnew;                              \
        else if (_dead)     _offfin = _dn;                                  \
        else                _offfin = (_dn - MAXGAP > _offnew)              \
                                        ? (_dn - MAXGAP) : _offnew;         \
        if (!_dead) {                                                       \
            float _f = exp2i(off - _offfin);                                \
            La_v *= _f; Lb_v *= _f; Ba *= _f; Bb *= _f; B64 *= _f;          \
        }                                                                   \
        off = _offfin;                                                      \
        int _dnf = __shfl_down_sync(FULL, _offfin, 1);                      \
        int _dd = _dnf - _offfin;                                           \
        if (_dd > 100) _dd = 100;                                           \
        corr = (lane == 31) ? 0.0f : exp2i(_dd);                            \
    } while (0)

#define DO_STEPS(STEPM)                                                 \
    do {                                                                \
        _Pragma("unroll")                                               \
        for (int _s = 0; _s < CH; ++_s) STEPM(va[_s], vb[_s], vq[_s]);  \
    } while (0)

    // Pipeline: prime 4 slots; steady state waits for slot c (3 younger
    // groups in flight), gathers it, refills with c+4, runs the DP chunk.
#define RUN_DIR(STEPM, RENM)                                            \
    do {                                                                \
        ISSUE_SLOT(0); ISSUE_SLOT(1); ISSUE_SLOT(2); ISSUE_SLOT(3);     \
        for (int c = 0; c <= NCH - 4; ++c) {                            \
            WAITG(3);                                                   \
            READ_SLOT(c);                                               \
            if (c + 4 < NCH) ISSUE_SLOT(c + 4);                         \
            DO_STEPS(STEPM); RENM();                                    \
        }                                                               \
        WAITG(2); READ_SLOT(NCH - 3); DO_STEPS(STEPM); RENM();          \
        WAITG(1); READ_SLOT(NCH - 2); DO_STEPS(STEPM); RENM();          \
        WAITG(0); READ_SLOT(NCH - 1); DO_STEPS(STEPM); RENM();          \
    } while (0)

    if (dir == 0) {
        // -------- forward: t = 0..255 --------
        Ba = (lane == 0) ? 1.0f : 0.0f;
        La_v = Lb_v = Bb = B64 = 0.0f;
        corr = (lane == 0) ? 0.0f : 1.0f;
        RUN_DIR(STEP_F, RENORM_F);
    } else {
        // -------- backward: t = 511..256 --------
        Ba = La_v = Bb = Lb_v = 0.0f;
        B64 = (lane == 31) ? 1.0f : 0.0f;
        corr = (lane == 31) ? 0.0f : 1.0f;
        RUN_DIR(STEP_B, RENORM_B);

        // Publish B_{256}(s) = beta(s) + beta(s+1) + skip(s+2)*beta(s+2)
        {
            float _nb = __shfl_down_sync(FULL, Ba, 1);
            float _nl = __shfl_down_sync(FULL, La_v, 1);
            _nb = (lane == 31) ? B64 : _nb * corr;
            _nl = (lane == 31) ? 0.0f : _nl * corr;
            sBv[lane][0] = Ba + La_v;                  // B at s=4j
            sBv[lane][1] = La_v + Bb + sb * Lb_v;      // B at s=4j+1
            sBv[lane][2] = Bb + Lb_v;                  // B at s=4j+2
            sBv[lane][3] = Lb_v + _nb + saN * _nl;     // B at s=4j+3
            sBv[lane][4] = B64;                        // B at s=128
            sBo[lane] = off;
        }
    }

    __syncthreads();

    if (dir == 0) {
        // dot over this lane's states; true value = dot * 2^(offA+offB)
        float dot = Ba * sBv[lane][0] + La_v * sBv[lane][1]
                  + Bb * sBv[lane][2] + Lb_v * sBv[lane][3];
        if (lane == 31) dot += B64 * sBv[lane][4];
        int e = off + sBo[lane];

        int   ep;    // normalized exponent of lane contribution
        float m;     // mantissa in [1,2)
        if (dot > 0.0f) {
            int ie = ((__float_as_int(dot) >> 23) & 255) - 127;
            m  = dot * exp2i(-ie);
            ep = e + ie;
        } else {
            m  = 0.0f;
            ep = -0x40000000;
        }
        int emax = ep;
#pragma unroll
        for (int o = 16; o > 0; o >>= 1)
            emax = max(emax, __shfl_xor_sync(FULL, emax, o));
        float part = m * exp2i(ep - emax);
#pragma unroll
        for (int o = 16; o > 0; o >>= 1)
            part += __shfl_xor_sync(FULL, part, o);
        if (lane == 0)
            out[b] = -((__log2f(part) + (float)emax) * LN2F);
    }
}

extern "C" void kernel_launch(void* const* d_in, const int* in_sizes, int n_in,
                              void* d_out, int out_size)
{
    // Identify inputs by element count: y_true is B*L int32, y_pred is B*T*V f32
    const int* y_true = nullptr;
    const float* y_pred = nullptr;
    if (in_sizes[0] == B_ * L_) {
        y_true = (const int*)d_in[0];
        y_pred = (const float*)d_in[1];
    } else {
        y_true = (const int*)d_in[1];
        y_pred = (const float*)d_in[0];
    }
    float* out = (float*)d_out;

    // 66.5KB dynamic smem ring per block (idempotent attribute set; not a
    // stream op, safe under graph capture)
    cudaFuncSetAttribute(ctc_forward_kernel,
                         cudaFuncAttributeMaxDynamicSharedMemorySize,
                         SMEM_DYN);

    // One 64-thread block per batch element: warp0 fwd DP, warp1 bwd DP
    ctc_forward_kernel<<<B_, 64, SMEM_DYN>>>(y_true, y_pred, out);
}